// round 4
// baseline (speedup 1.0000x reference)
#include <cuda_runtime.h>
#include <cuda_bf16.h>

#define NN 100000
#define NE 3200000
#define NBLK 98              // ceil(NN / 1024)

// ---------------- scratch (device globals: allocation-free) ----------------
__device__ int2   g_edges[NE];    // packed (row=dst, col=src)
__device__ int    g_cnt[NN];      // per-destination edge count
__device__ int    g_deg[NN];      // per-source degree (+1 self-loop)
__device__ float  g_dinv[NN];
__device__ int    g_start[NN + 1];// CSR offsets (by destination)
__device__ int    g_pos[NN];      // bucket cursors
__device__ int    g_bsum[NBLK];   // scan block sums
__device__ int    g_col[NE];      // CSR adjacency (source ids)
__device__ float4 g_tA[NN];       // ping-pong scaled feature tables
__device__ float4 g_tB[NN];
__device__ float2 g_t2[NN];
__device__ int    g_idx32;        // 1 if edge_index is int32

// ---------------- dtype detection (parallel, 1 warp) ----------------
__global__ void k_detect(const long long* __restrict__ ei) {
    long long v = ei[threadIdx.x];
    unsigned bad = __ballot_sync(0xffffffffu, v < 0 || v >= NN);
    if (threadIdx.x == 0) g_idx32 = bad ? 1 : 0;
}

// ---------------- zero/init ----------------
__global__ void k_zero() {
    int v = blockIdx.x * blockDim.x + threadIdx.x;
    if (v < NN) { g_cnt[v] = 0; g_deg[v] = 1; }   // deg starts at 1 (self-loop)
}

// ---------------- edge pass 1: pack + histograms ----------------
__global__ void __launch_bounds__(256) k_count(const void* __restrict__ eiv) {
    int e = blockIdx.x * 256 + threadIdx.x;
    if (e >= NE) return;
    int r, c;
    if (g_idx32) {
        const int* ei = (const int*)eiv;
        r = ei[e]; c = ei[NE + e];
    } else {
        const long long* ei = (const long long*)eiv;
        r = (int)ei[e]; c = (int)ei[NE + e];
    }
    g_edges[e] = make_int2(r, c);
    atomicAdd(&g_cnt[r], 1);      // CSR bucket sizes (destination)
    atomicAdd(&g_deg[c], 1);      // normalization degree (source)
}

// ---------------- exclusive scan of g_cnt (2-level) + fused dinv ----------------
__global__ void __launch_bounds__(1024) k_scan1() {
    int tid = threadIdx.x;
    int v = blockIdx.x * 1024 + tid;
    int val = (v < NN) ? g_cnt[v] : 0;
    int lane = tid & 31, w = tid >> 5;
    int inc = val;
    #pragma unroll
    for (int o = 1; o < 32; o <<= 1) {
        int t = __shfl_up_sync(0xffffffffu, inc, o);
        if (lane >= o) inc += t;
    }
    __shared__ int ws[32];
    if (lane == 31) ws[w] = inc;
    __syncthreads();
    if (w == 0) {
        int s = ws[lane];
        int si = s;
        #pragma unroll
        for (int o = 1; o < 32; o <<= 1) {
            int t = __shfl_up_sync(0xffffffffu, si, o);
            if (lane >= o) si += t;
        }
        ws[lane] = si - s;        // exclusive warp offsets
    }
    __syncthreads();
    int excl = inc - val + ws[w];
    if (v < NN) {
        g_start[v] = excl;
        g_dinv[v] = rsqrtf((float)g_deg[v]);
    }
    if (tid == 1023) g_bsum[blockIdx.x] = excl + val;
}

__global__ void k_scan2() {
    __shared__ int s[128];
    int tid = threadIdx.x;
    int val = (tid < NBLK) ? g_bsum[tid] : 0;
    s[tid] = val;
    __syncthreads();
    for (int o = 1; o < 128; o <<= 1) {
        int t = (tid >= o) ? s[tid - o] : 0;
        __syncthreads();
        s[tid] += t;
        __syncthreads();
    }
    if (tid < NBLK) g_bsum[tid] = s[tid] - val;   // exclusive
}

__global__ void k_scan3() {
    int v = blockIdx.x * blockDim.x + threadIdx.x;
    if (v < NN) {
        int f = g_start[v] + g_bsum[v >> 10];
        g_start[v] = f;
        g_pos[v] = f;
    }
    if (v == 0) g_start[NN] = NE;
}

// ---------------- edge pass 2: bucket into CSR ----------------
__global__ void __launch_bounds__(256) k_bucket() {
    int e = blockIdx.x * 256 + threadIdx.x;
    if (e >= NE) return;
    int2 rc = g_edges[e];
    int slot = atomicAdd(&g_pos[rc.x], 1);
    g_col[slot] = rc.y;
}

// ---------------- layer 1 transform: tA = (x @ W1) * dinv ----------------
__global__ void __launch_bounds__(256) k_l1(const float* __restrict__ x,
                                            const float* __restrict__ W1) {
    __shared__ float sW[512];
    for (int i = threadIdx.x; i < 512; i += 256) sW[i] = W1[i];
    __syncthreads();
    int gw   = (blockIdx.x * 256 + threadIdx.x) >> 5;
    int lane = threadIdx.x & 31;
    if (gw >= NN) return;
    float4 xr = __ldg((const float4*)x + (size_t)gw * 32 + lane);
    float xs[4] = {xr.x, xr.y, xr.z, xr.w};
    float acc[4] = {0.f, 0.f, 0.f, 0.f};
    #pragma unroll
    for (int i = 0; i < 4; i++) {
        int k = lane * 4 + i;
        #pragma unroll
        for (int j = 0; j < 4; j++) acc[j] += xs[i] * sW[k * 4 + j];
    }
    #pragma unroll
    for (int off = 16; off > 0; off >>= 1) {
        #pragma unroll
        for (int j = 0; j < 4; j++)
            acc[j] += __shfl_xor_sync(0xffffffffu, acc[j], off);
    }
    if (lane == 0) {
        float d = g_dinv[gw];
        g_tA[gw] = make_float4(acc[0] * d, acc[1] * d, acc[2] * d, acc[3] * d);
    }
}

// ---------------- gather-aggregate layers (warp per node, fused epilogue) ------
__global__ void __launch_bounds__(256) k_agg1(const float* __restrict__ W2,
                                              const float* __restrict__ b1) {
    int gw   = (blockIdx.x * 256 + threadIdx.x) >> 5;
    int lane = threadIdx.x & 31;
    if (gw >= NN) return;
    int s = g_start[gw], e = g_start[gw + 1];
    float4 acc = make_float4(0.f, 0.f, 0.f, 0.f);
    for (int i = s + lane; i < e; i += 32) {
        float4 u = __ldg(g_tA + __ldg(g_col + i));
        acc.x += u.x; acc.y += u.y; acc.z += u.z; acc.w += u.w;
    }
    #pragma unroll
    for (int o = 16; o > 0; o >>= 1) {
        acc.x += __shfl_xor_sync(0xffffffffu, acc.x, o);
        acc.y += __shfl_xor_sync(0xffffffffu, acc.y, o);
        acc.z += __shfl_xor_sync(0xffffffffu, acc.z, o);
        acc.w += __shfl_xor_sync(0xffffffffu, acc.w, o);
    }
    if (lane == 0) {
        float4 self = g_tA[gw];
        float d = g_dinv[gw];
        float h0 = tanhf(fmaf(acc.x + self.x, d, __ldg(b1 + 0)));
        float h1 = tanhf(fmaf(acc.y + self.y, d, __ldg(b1 + 1)));
        float h2 = tanhf(fmaf(acc.z + self.z, d, __ldg(b1 + 2)));
        float h3 = tanhf(fmaf(acc.w + self.w, d, __ldg(b1 + 3)));
        float t[4];
        #pragma unroll
        for (int j = 0; j < 4; j++)
            t[j] = (h0 * __ldg(W2 + j)      + h1 * __ldg(W2 + 4 + j)
                  + h2 * __ldg(W2 + 8 + j)  + h3 * __ldg(W2 + 12 + j)) * d;
        g_tB[gw] = make_float4(t[0], t[1], t[2], t[3]);
    }
}

__global__ void __launch_bounds__(256) k_agg2(const float* __restrict__ W3,
                                              const float* __restrict__ b2) {
    int gw   = (blockIdx.x * 256 + threadIdx.x) >> 5;
    int lane = threadIdx.x & 31;
    if (gw >= NN) return;
    int s = g_start[gw], e = g_start[gw + 1];
    float4 acc = make_float4(0.f, 0.f, 0.f, 0.f);
    for (int i = s + lane; i < e; i += 32) {
        float4 u = __ldg(g_tB + __ldg(g_col + i));
        acc.x += u.x; acc.y += u.y; acc.z += u.z; acc.w += u.w;
    }
    #pragma unroll
    for (int o = 16; o > 0; o >>= 1) {
        acc.x += __shfl_xor_sync(0xffffffffu, acc.x, o);
        acc.y += __shfl_xor_sync(0xffffffffu, acc.y, o);
        acc.z += __shfl_xor_sync(0xffffffffu, acc.z, o);
        acc.w += __shfl_xor_sync(0xffffffffu, acc.w, o);
    }
    if (lane == 0) {
        float4 self = g_tB[gw];
        float d = g_dinv[gw];
        float h0 = tanhf(fmaf(acc.x + self.x, d, __ldg(b2 + 0)));
        float h1 = tanhf(fmaf(acc.y + self.y, d, __ldg(b2 + 1)));
        float h2 = tanhf(fmaf(acc.z + self.z, d, __ldg(b2 + 2)));
        float h3 = tanhf(fmaf(acc.w + self.w, d, __ldg(b2 + 3)));
        float t0 = (h0 * __ldg(W3 + 0) + h1 * __ldg(W3 + 2)
                  + h2 * __ldg(W3 + 4) + h3 * __ldg(W3 + 6)) * d;
        float t1 = (h0 * __ldg(W3 + 1) + h1 * __ldg(W3 + 3)
                  + h2 * __ldg(W3 + 5) + h3 * __ldg(W3 + 7)) * d;
        g_t2[gw] = make_float2(t0, t1);
    }
}

__global__ void __launch_bounds__(256) k_agg3(const float* __restrict__ b3,
                                              const float* __restrict__ Wc,
                                              const float* __restrict__ bc,
                                              float* __restrict__ out,
                                              int write_h) {
    int gw   = (blockIdx.x * 256 + threadIdx.x) >> 5;
    int lane = threadIdx.x & 31;
    if (gw >= NN) return;
    int s = g_start[gw], e = g_start[gw + 1];
    float2 acc = make_float2(0.f, 0.f);
    for (int i = s + lane; i < e; i += 32) {
        float2 u = __ldg(g_t2 + __ldg(g_col + i));
        acc.x += u.x; acc.y += u.y;
    }
    #pragma unroll
    for (int o = 16; o > 0; o >>= 1) {
        acc.x += __shfl_xor_sync(0xffffffffu, acc.x, o);
        acc.y += __shfl_xor_sync(0xffffffffu, acc.y, o);
    }
    if (lane == 0) {
        float2 self = g_t2[gw];
        float d = g_dinv[gw];
        float h0 = tanhf(fmaf(acc.x + self.x, d, __ldg(b3 + 0)));
        float h1 = tanhf(fmaf(acc.y + self.y, d, __ldg(b3 + 1)));
        float4 o4;
        o4.x = h0 * __ldg(Wc + 0) + h1 * __ldg(Wc + 4) + __ldg(bc + 0);
        o4.y = h0 * __ldg(Wc + 1) + h1 * __ldg(Wc + 5) + __ldg(bc + 1);
        o4.z = h0 * __ldg(Wc + 2) + h1 * __ldg(Wc + 6) + __ldg(bc + 2);
        o4.w = h0 * __ldg(Wc + 3) + h1 * __ldg(Wc + 7) + __ldg(bc + 3);
        ((float4*)out)[gw] = o4;
        if (write_h)
            ((float2*)(out + 4 * NN))[gw] = make_float2(h0, h1);
    }
}

// ---------------- host ----------------
extern "C" void kernel_launch(void* const* d_in, const int* in_sizes, int n_in,
                              void* d_out, int out_size) {
    const float* x  = (const float*)d_in[0];
    const void*  ei = d_in[1];
    const float* W1 = (const float*)d_in[2];
    const float* b1 = (const float*)d_in[3];
    const float* W2 = (const float*)d_in[4];
    const float* b2 = (const float*)d_in[5];
    const float* W3 = (const float*)d_in[6];
    const float* b3 = (const float*)d_in[7];
    const float* Wc = (const float*)d_in[8];
    const float* bc = (const float*)d_in[9];
    float* out = (float*)d_out;

    const int nbN = (NN + 255) / 256;
    const int nbE = (NE + 255) / 256;
    const int nbW = (NN * 32 + 255) / 256;   // warp per node
    const int write_h = (out_size >= 6 * NN) ? 1 : 0;

    k_detect<<<1, 32>>>((const long long*)ei);
    k_zero  <<<nbN, 256>>>();
    k_count <<<nbE, 256>>>(ei);
    k_scan1 <<<NBLK, 1024>>>();
    k_scan2 <<<1, 128>>>();
    k_scan3 <<<nbN, 256>>>();
    k_bucket<<<nbE, 256>>>();

    k_l1  <<<nbW, 256>>>(x, W1);
    k_agg1<<<nbW, 256>>>(W2, b1);
    k_agg2<<<nbW, 256>>>(W3, b2);
    k_agg3<<<nbW, 256>>>(b3, Wc, bc, out, write_h);
}

// round 6
// speedup vs baseline: 1.3814x; 1.3814x over previous
#include <cuda_runtime.h>
#include <cuda_bf16.h>

#define NN 100000
#define NE 3200000

// ---------------- scratch (device globals: allocation-free) ----------------
__device__ int2   g_edges[NE];   // packed (row=dst, col=src) as int32
__device__ int    g_deg[NN];
__device__ float4 g_t4[NN];      // current layer's scaled node features (gather source)
__device__ float4 g_aggA[NN];    // layer-1 accumulator
__device__ float4 g_aggB[NN];    // layer-2 accumulator
__device__ float2 g_t2[NN];      // layer-3 scaled features
__device__ float2 g_agg2[NN];    // layer-3 accumulator
__device__ int    g_idx32;       // 1 if edge_index is int32, 0 if int64

// ---------------- detect dtype (1 warp, parallel) + init degrees ----------------
__global__ void k_init(const long long* __restrict__ ei) {
    int v = blockIdx.x * blockDim.x + threadIdx.x;
    if (v < NN) g_deg[v] = 1;                       // self-loop
    if (blockIdx.x == 0 && threadIdx.x < 32) {
        long long val = ei[threadIdx.x];
        unsigned bad = __ballot_sync(0xffffffffu, val < 0 || val >= NN);
        if (threadIdx.x == 0) g_idx32 = bad ? 1 : 0;
    }
}

// ---------------- edge pass: pack + degree histogram ----------------
__global__ void __launch_bounds__(256) k_pre(const void* __restrict__ eiv) {
    int e = blockIdx.x * 256 + threadIdx.x;
    if (e >= NE) return;
    int r, c;
    if (g_idx32) {
        const int* ei = (const int*)eiv;
        r = ei[e]; c = ei[NE + e];
    } else {
        const long long* ei = (const long long*)eiv;
        r = (int)ei[e]; c = (int)ei[NE + e];
    }
    g_edges[e] = make_int2(r, c);
    atomicAdd(&g_deg[c], 1);      // degree counts SOURCE occurrences (matches ref)
}

// ---------------- layer 1 transform: t = (x @ W1) * dinv ; aggA = t ----------------
// warp per node; 128 features; thread handles 4 features
__global__ void __launch_bounds__(256) k_l1(const float* __restrict__ x,
                                            const float* __restrict__ W1) {
    __shared__ float sW[512];            // W1 [128,4] row-major
    for (int i = threadIdx.x; i < 512; i += 256) sW[i] = W1[i];
    __syncthreads();
    int gw   = (blockIdx.x * 256 + threadIdx.x) >> 5;   // node
    int lane = threadIdx.x & 31;
    if (gw >= NN) return;
    float4 xr = __ldg((const float4*)x + (size_t)gw * 32 + lane);
    float xs[4] = {xr.x, xr.y, xr.z, xr.w};
    float acc[4] = {0.f, 0.f, 0.f, 0.f};
    #pragma unroll
    for (int i = 0; i < 4; i++) {
        int k = lane * 4 + i;
        #pragma unroll
        for (int j = 0; j < 4; j++) acc[j] += xs[i] * sW[k * 4 + j];
    }
    #pragma unroll
    for (int off = 16; off > 0; off >>= 1) {
        #pragma unroll
        for (int j = 0; j < 4; j++)
            acc[j] += __shfl_xor_sync(0xffffffffu, acc[j], off);
    }
    if (lane == 0) {
        float d  = rsqrtf((float)g_deg[gw]);
        float4 t = make_float4(acc[0] * d, acc[1] * d, acc[2] * d, acc[3] * d);
        g_t4[gw]   = t;
        g_aggA[gw] = t;                 // self-loop contribution
    }
}

// ---------------- edge scatter: agg[row] += t[col]  (2 edges / thread, MLP) ------
template <int PHASE>   // 0: agg=aggA, 1: agg=aggB
__global__ void __launch_bounds__(256) k_scatter4() {
    int base = (blockIdx.x * 256 + threadIdx.x) * 2;
    float4* agg = (PHASE == 0) ? g_aggA : g_aggB;
    if (base + 1 < NE) {
        int2 rc0 = g_edges[base];
        int2 rc1 = g_edges[base + 1];
        float4 v0 = __ldg(g_t4 + rc0.y);
        float4 v1 = __ldg(g_t4 + rc1.y);
        asm volatile("red.global.add.v4.f32 [%0], {%1, %2, %3, %4};"
                     :: "l"(agg + rc0.x), "f"(v0.x), "f"(v0.y), "f"(v0.z), "f"(v0.w)
                     : "memory");
        asm volatile("red.global.add.v4.f32 [%0], {%1, %2, %3, %4};"
                     :: "l"(agg + rc1.x), "f"(v1.x), "f"(v1.y), "f"(v1.z), "f"(v1.w)
                     : "memory");
    } else if (base < NE) {
        int2 rc = g_edges[base];
        float4 v = __ldg(g_t4 + rc.y);
        asm volatile("red.global.add.v4.f32 [%0], {%1, %2, %3, %4};"
                     :: "l"(agg + rc.x), "f"(v.x), "f"(v.y), "f"(v.z), "f"(v.w)
                     : "memory");
    }
}

__global__ void __launch_bounds__(256) k_scatter2() {
    int base = (blockIdx.x * 256 + threadIdx.x) * 2;
    if (base + 1 < NE) {
        int2 rc0 = g_edges[base];
        int2 rc1 = g_edges[base + 1];
        float2 v0 = __ldg(g_t2 + rc0.y);
        float2 v1 = __ldg(g_t2 + rc1.y);
        asm volatile("red.global.add.v2.f32 [%0], {%1, %2};"
                     :: "l"(g_agg2 + rc0.x), "f"(v0.x), "f"(v0.y) : "memory");
        asm volatile("red.global.add.v2.f32 [%0], {%1, %2};"
                     :: "l"(g_agg2 + rc1.x), "f"(v1.x), "f"(v1.y) : "memory");
    } else if (base < NE) {
        int2 rc = g_edges[base];
        float2 v = __ldg(g_t2 + rc.y);
        asm volatile("red.global.add.v2.f32 [%0], {%1, %2};"
                     :: "l"(g_agg2 + rc.x), "f"(v.x), "f"(v.y) : "memory");
    }
}

// ---------------- layer 2 transform ----------------
__global__ void __launch_bounds__(256) k_l2(const float* __restrict__ W2,
                                            const float* __restrict__ b1) {
    int v = blockIdx.x * blockDim.x + threadIdx.x;
    if (v >= NN) return;
    float d  = rsqrtf((float)g_deg[v]);
    float4 a = g_aggA[v];
    float h0 = tanhf(fmaf(a.x, d, __ldg(b1 + 0)));
    float h1 = tanhf(fmaf(a.y, d, __ldg(b1 + 1)));
    float h2 = tanhf(fmaf(a.z, d, __ldg(b1 + 2)));
    float h3 = tanhf(fmaf(a.w, d, __ldg(b1 + 3)));
    float t[4];
    #pragma unroll
    for (int j = 0; j < 4; j++)
        t[j] = (h0 * __ldg(W2 + j)     + h1 * __ldg(W2 + 4 + j)
              + h2 * __ldg(W2 + 8 + j) + h3 * __ldg(W2 + 12 + j)) * d;
    float4 tv = make_float4(t[0], t[1], t[2], t[3]);
    g_t4[v]   = tv;
    g_aggB[v] = tv;
}

// ---------------- layer 3 transform ----------------
__global__ void __launch_bounds__(256) k_l3(const float* __restrict__ W3,
                                            const float* __restrict__ b2) {
    int v = blockIdx.x * blockDim.x + threadIdx.x;
    if (v >= NN) return;
    float d  = rsqrtf((float)g_deg[v]);
    float4 a = g_aggB[v];
    float h0 = tanhf(fmaf(a.x, d, __ldg(b2 + 0)));
    float h1 = tanhf(fmaf(a.y, d, __ldg(b2 + 1)));
    float h2 = tanhf(fmaf(a.z, d, __ldg(b2 + 2)));
    float h3 = tanhf(fmaf(a.w, d, __ldg(b2 + 3)));
    float t0 = (h0 * __ldg(W3 + 0) + h1 * __ldg(W3 + 2)
              + h2 * __ldg(W3 + 4) + h3 * __ldg(W3 + 6)) * d;
    float t1 = (h0 * __ldg(W3 + 1) + h1 * __ldg(W3 + 3)
              + h2 * __ldg(W3 + 5) + h3 * __ldg(W3 + 7)) * d;
    float2 tv = make_float2(t0, t1);
    g_t2[v]   = tv;
    g_agg2[v] = tv;
}

// ---------------- epilogue ----------------
__global__ void __launch_bounds__(256) k_final(const float* __restrict__ b3,
                                               const float* __restrict__ Wc,
                                               const float* __restrict__ bc,
                                               float* __restrict__ out,
                                               int write_h) {
    int v = blockIdx.x * blockDim.x + threadIdx.x;
    if (v >= NN) return;
    float d  = rsqrtf((float)g_deg[v]);
    float2 a = g_agg2[v];
    float h0 = tanhf(fmaf(a.x, d, __ldg(b3 + 0)));
    float h1 = tanhf(fmaf(a.y, d, __ldg(b3 + 1)));
    float4 o;
    o.x = h0 * __ldg(Wc + 0) + h1 * __ldg(Wc + 4) + __ldg(bc + 0);
    o.y = h0 * __ldg(Wc + 1) + h1 * __ldg(Wc + 5) + __ldg(bc + 1);
    o.z = h0 * __ldg(Wc + 2) + h1 * __ldg(Wc + 6) + __ldg(bc + 2);
    o.w = h0 * __ldg(Wc + 3) + h1 * __ldg(Wc + 7) + __ldg(bc + 3);
    ((float4*)out)[v] = o;                                  // out [N,4]
    if (write_h)
        ((float2*)(out + 4 * NN))[v] = make_float2(h0, h1); // h [N,2]
}

// ---------------- host ----------------
extern "C" void kernel_launch(void* const* d_in, const int* in_sizes, int n_in,
                              void* d_out, int out_size) {
    const float* x  = (const float*)d_in[0];
    const void*  ei = d_in[1];
    const float* W1 = (const float*)d_in[2];
    const float* b1 = (const float*)d_in[3];
    const float* W2 = (const float*)d_in[4];
    const float* b2 = (const float*)d_in[5];
    const float* W3 = (const float*)d_in[6];
    const float* b3 = (const float*)d_in[7];
    const float* Wc = (const float*)d_in[8];
    const float* bc = (const float*)d_in[9];
    float* out = (float*)d_out;

    const int nbN  = (NN + 255) / 256;
    const int nbE  = (NE + 255) / 256;
    const int nbE2 = (NE + 511) / 512;          // 2 edges / thread
    const int nbW  = (NN + 7) / 8;              // warp-per-node, 8 warps/block
    const int write_h = (out_size >= 6 * NN) ? 1 : 0;

    k_init<<<nbN, 256>>>((const long long*)ei);
    k_pre <<<nbE, 256>>>(ei);

    k_l1         <<<nbW, 256>>>(x, W1);
    k_scatter4<0><<<nbE2, 256>>>();

    k_l2         <<<nbN, 256>>>(W2, b1);
    k_scatter4<1><<<nbE2, 256>>>();

    k_l3         <<<nbN, 256>>>(W3, b2);
    k_scatter2   <<<nbE2, 256>>>();

    k_final      <<<nbN, 256>>>(b3, Wc, bc, out, write_h);
}

// round 7
// speedup vs baseline: 1.4276x; 1.0335x over previous
#include <cuda_runtime.h>
#include <cuda_bf16.h>

#define NN 100000
#define NE 3200000

// ---------------- scratch (device globals: allocation-free) ----------------
__device__ int2   g_edges[NE];   // packed edges (only used on the int64 path)
__device__ int    g_deg[NN];
__device__ float4 g_t4[NN];      // current layer's scaled node features (gather source)
__device__ float4 g_aggA[NN];    // layer-1 accumulator
__device__ float4 g_aggB[NN];    // layer-2 accumulator
__device__ float2 g_t2[NN];      // layer-3 scaled features
__device__ float2 g_agg2[NN];    // layer-3 accumulator
__device__ int    g_idx32;       // 1 if edge_index is int32, 0 if int64

// ---------------- detect dtype (1 warp, parallel) + init degrees ----------------
__global__ void k_init(const long long* __restrict__ ei) {
    int v = blockIdx.x * blockDim.x + threadIdx.x;
    if (v < NN) g_deg[v] = 1;                       // self-loop
    if (blockIdx.x == 0 && threadIdx.x < 32) {
        long long val = ei[threadIdx.x];
        unsigned bad = __ballot_sync(0xffffffffu, val < 0 || val >= NN);
        if (threadIdx.x == 0) g_idx32 = bad ? 1 : 0;
    }
}

// ---------------- edge pass: degree histogram (+ pack only for int64) ----------
__global__ void __launch_bounds__(256) k_pre(const void* __restrict__ eiv) {
    int t = blockIdx.x * 256 + threadIdx.x;
    if (g_idx32) {
        int base = t * 4;
        if (base >= NE) return;                     // only first 1/4 of blocks active
        int4 cc = __ldg((const int4*)((const int*)eiv + NE + base));
        atomicAdd(&g_deg[cc.x], 1);
        atomicAdd(&g_deg[cc.y], 1);
        atomicAdd(&g_deg[cc.z], 1);
        atomicAdd(&g_deg[cc.w], 1);
    } else {
        if (t >= NE) return;
        const long long* ei = (const long long*)eiv;
        int r = (int)ei[t];
        int c = (int)ei[NE + t];
        g_edges[t] = make_int2(r, c);
        atomicAdd(&g_deg[c], 1);
    }
}

// ---------------- layer 1 transform: t = (x @ W1) * dinv ; aggA = t ------------
__global__ void __launch_bounds__(256) k_l1(const float* __restrict__ x,
                                            const float* __restrict__ W1) {
    __shared__ float sW[512];            // W1 [128,4] row-major
    for (int i = threadIdx.x; i < 512; i += 256) sW[i] = W1[i];
    __syncthreads();
    int gw   = (blockIdx.x * 256 + threadIdx.x) >> 5;   // node
    int lane = threadIdx.x & 31;
    if (gw >= NN) return;
    float4 xr = __ldg((const float4*)x + (size_t)gw * 32 + lane);
    float xs[4] = {xr.x, xr.y, xr.z, xr.w};
    float acc[4] = {0.f, 0.f, 0.f, 0.f};
    #pragma unroll
    for (int i = 0; i < 4; i++) {
        int k = lane * 4 + i;
        #pragma unroll
        for (int j = 0; j < 4; j++) acc[j] += xs[i] * sW[k * 4 + j];
    }
    #pragma unroll
    for (int off = 16; off > 0; off >>= 1) {
        #pragma unroll
        for (int j = 0; j < 4; j++)
            acc[j] += __shfl_xor_sync(0xffffffffu, acc[j], off);
    }
    if (lane == 0) {
        float d  = rsqrtf((float)g_deg[gw]);
        float4 t = make_float4(acc[0] * d, acc[1] * d, acc[2] * d, acc[3] * d);
        g_t4[gw]   = t;
        g_aggA[gw] = t;                 // self-loop contribution
    }
}

// ---------------- edge scatter: agg[row] += t[col]  (4 edges/thread) -----------
template <int PHASE>   // 0: agg=aggA, 1: agg=aggB
__global__ void __launch_bounds__(256) k_scatter4(const int* __restrict__ ei32) {
    int base = (blockIdx.x * 256 + threadIdx.x) * 4;
    if (base >= NE) return;
    int r[4], c[4];
    if (g_idx32) {
        int4 rr = __ldg((const int4*)(ei32 + base));
        int4 cc = __ldg((const int4*)(ei32 + NE + base));
        r[0] = rr.x; r[1] = rr.y; r[2] = rr.z; r[3] = rr.w;
        c[0] = cc.x; c[1] = cc.y; c[2] = cc.z; c[3] = cc.w;
    } else {
        int4 p0 = *(const int4*)(g_edges + base);
        int4 p1 = *(const int4*)(g_edges + base + 2);
        r[0] = p0.x; c[0] = p0.y; r[1] = p0.z; c[1] = p0.w;
        r[2] = p1.x; c[2] = p1.y; r[3] = p1.z; c[3] = p1.w;
    }
    float4 v[4];
    #pragma unroll
    for (int i = 0; i < 4; i++) v[i] = __ldg(g_t4 + c[i]);
    float4* agg = (PHASE == 0) ? g_aggA : g_aggB;
    #pragma unroll
    for (int i = 0; i < 4; i++)
        asm volatile("red.global.add.v4.f32 [%0], {%1, %2, %3, %4};"
                     :: "l"(agg + r[i]), "f"(v[i].x), "f"(v[i].y), "f"(v[i].z), "f"(v[i].w)
                     : "memory");
}

__global__ void __launch_bounds__(256) k_scatter2(const int* __restrict__ ei32) {
    int base = (blockIdx.x * 256 + threadIdx.x) * 4;
    if (base >= NE) return;
    int r[4], c[4];
    if (g_idx32) {
        int4 rr = __ldg((const int4*)(ei32 + base));
        int4 cc = __ldg((const int4*)(ei32 + NE + base));
        r[0] = rr.x; r[1] = rr.y; r[2] = rr.z; r[3] = rr.w;
        c[0] = cc.x; c[1] = cc.y; c[2] = cc.z; c[3] = cc.w;
    } else {
        int4 p0 = *(const int4*)(g_edges + base);
        int4 p1 = *(const int4*)(g_edges + base + 2);
        r[0] = p0.x; c[0] = p0.y; r[1] = p0.z; c[1] = p0.w;
        r[2] = p1.x; c[2] = p1.y; r[3] = p1.z; c[3] = p1.w;
    }
    float2 v[4];
    #pragma unroll
    for (int i = 0; i < 4; i++) v[i] = __ldg(g_t2 + c[i]);
    #pragma unroll
    for (int i = 0; i < 4; i++)
        asm volatile("red.global.add.v2.f32 [%0], {%1, %2};"
                     :: "l"(g_agg2 + r[i]), "f"(v[i].x), "f"(v[i].y) : "memory");
}

// ---------------- layer 2 transform ----------------
__global__ void __launch_bounds__(256) k_l2(const float* __restrict__ W2,
                                            const float* __restrict__ b1) {
    int v = blockIdx.x * blockDim.x + threadIdx.x;
    if (v >= NN) return;
    float d  = rsqrtf((float)g_deg[v]);
    float4 a = g_aggA[v];
    float h0 = tanhf(fmaf(a.x, d, __ldg(b1 + 0)));
    float h1 = tanhf(fmaf(a.y, d, __ldg(b1 + 1)));
    float h2 = tanhf(fmaf(a.z, d, __ldg(b1 + 2)));
    float h3 = tanhf(fmaf(a.w, d, __ldg(b1 + 3)));
    float t[4];
    #pragma unroll
    for (int j = 0; j < 4; j++)
        t[j] = (h0 * __ldg(W2 + j)     + h1 * __ldg(W2 + 4 + j)
              + h2 * __ldg(W2 + 8 + j) + h3 * __ldg(W2 + 12 + j)) * d;
    float4 tv = make_float4(t[0], t[1], t[2], t[3]);
    g_t4[v]   = tv;
    g_aggB[v] = tv;
}

// ---------------- layer 3 transform ----------------
__global__ void __launch_bounds__(256) k_l3(const float* __restrict__ W3,
                                            const float* __restrict__ b2) {
    int v = blockIdx.x * blockDim.x + threadIdx.x;
    if (v >= NN) return;
    float d  = rsqrtf((float)g_deg[v]);
    float4 a = g_aggB[v];
    float h0 = tanhf(fmaf(a.x, d, __ldg(b2 + 0)));
    float h1 = tanhf(fmaf(a.y, d, __ldg(b2 + 1)));
    float h2 = tanhf(fmaf(a.z, d, __ldg(b2 + 2)));
    float h3 = tanhf(fmaf(a.w, d, __ldg(b2 + 3)));
    float t0 = (h0 * __ldg(W3 + 0) + h1 * __ldg(W3 + 2)
              + h2 * __ldg(W3 + 4) + h3 * __ldg(W3 + 6)) * d;
    float t1 = (h0 * __ldg(W3 + 1) + h1 * __ldg(W3 + 3)
              + h2 * __ldg(W3 + 5) + h3 * __ldg(W3 + 7)) * d;
    float2 tv = make_float2(t0, t1);
    g_t2[v]   = tv;
    g_agg2[v] = tv;
}

// ---------------- epilogue ----------------
__global__ void __launch_bounds__(256) k_final(const float* __restrict__ b3,
                                               const float* __restrict__ Wc,
                                               const float* __restrict__ bc,
                                               float* __restrict__ out,
                                               int write_h) {
    int v = blockIdx.x * blockDim.x + threadIdx.x;
    if (v >= NN) return;
    float d  = rsqrtf((float)g_deg[v]);
    float2 a = g_agg2[v];
    float h0 = tanhf(fmaf(a.x, d, __ldg(b3 + 0)));
    float h1 = tanhf(fmaf(a.y, d, __ldg(b3 + 1)));
    float4 o;
    o.x = h0 * __ldg(Wc + 0) + h1 * __ldg(Wc + 4) + __ldg(bc + 0);
    o.y = h0 * __ldg(Wc + 1) + h1 * __ldg(Wc + 5) + __ldg(bc + 1);
    o.z = h0 * __ldg(Wc + 2) + h1 * __ldg(Wc + 6) + __ldg(bc + 2);
    o.w = h0 * __ldg(Wc + 3) + h1 * __ldg(Wc + 7) + __ldg(bc + 3);
    ((float4*)out)[v] = o;                                  // out [N,4]
    if (write_h)
        ((float2*)(out + 4 * NN))[v] = make_float2(h0, h1); // h [N,2]
}

// ---------------- host ----------------
extern "C" void kernel_launch(void* const* d_in, const int* in_sizes, int n_in,
                              void* d_out, int out_size) {
    const float* x  = (const float*)d_in[0];
    const void*  ei = d_in[1];
    const float* W1 = (const float*)d_in[2];
    const float* b1 = (const float*)d_in[3];
    const float* W2 = (const float*)d_in[4];
    const float* b2 = (const float*)d_in[5];
    const float* W3 = (const float*)d_in[6];
    const float* b3 = (const float*)d_in[7];
    const float* Wc = (const float*)d_in[8];
    const float* bc = (const float*)d_in[9];
    float* out = (float*)d_out;

    const int nbN  = (NN + 255) / 256;
    const int nbE  = (NE + 255) / 256;          // int64 pack path coverage
    const int nbE4 = NE / (256 * 4);            // 4 edges/thread (exact: 3125)
    const int nbW  = (NN + 7) / 8;              // warp-per-node, 8 warps/block
    const int write_h = (out_size >= 6 * NN) ? 1 : 0;

    k_init<<<nbN, 256>>>((const long long*)ei);
    k_pre <<<nbE, 256>>>(ei);

    k_l1         <<<nbW, 256>>>(x, W1);
    k_scatter4<0><<<nbE4, 256>>>((const int*)ei);

    k_l2         <<<nbN, 256>>>(W2, b1);
    k_scatter4<1><<<nbE4, 256>>>((const int*)ei);

    k_l3         <<<nbN, 256>>>(W3, b2);
    k_scatter2   <<<nbE4, 256>>>((const int*)ei);

    k_final      <<<nbN, 256>>>(b3, Wc, bc, out, write_h);
}